// round 10
// baseline (speedup 1.0000x reference)
#include <cuda_runtime.h>
#include <stdint.h>

// out[b] = sum_{s=0}^{199} w_weight[text[s,b]] + bias
// text (200, 2048) row-major, tokens in [0, 50000)
#define S_TOK 200
#define B_PHR 2048
#define V_SZ  50000
#define CH0_FLOATS 37500                // chunk0: 150000 B (16B multiple)
#define CH0_BYTES  (CH0_FLOATS * 4)
#define CH1_BYTES  (V_SZ * 4 - CH0_BYTES)   // 50000 B
#define PHR_PER_BLK 32
#define NBLK (B_PHR / PHR_PER_BLK)      // 64 blocks, single wave
#define NTHR 1024
#define NGRP 32
#define RED_FLOATS (NGRP * PHR_PER_BLK) // 1024
#define SMEM_BYTES (V_SZ * 4 + RED_FLOATS * 4 + 2 * 8 + 8)

__device__ __forceinline__ uint32_t smem_u32(const void* p) {
    uint32_t a;
    asm("{ .reg .u64 t; cvta.to.shared.u64 t, %1; cvt.u32.u64 %0, t; }"
        : "=r"(a) : "l"(p));
    return a;
}

__device__ __forceinline__ void mbar_wait0(uint32_t mbar_a) {
    uint32_t done;
    asm volatile(
        "{\n\t.reg .pred P;\n\t"
        "mbarrier.try_wait.parity.acquire.cta.shared::cta.b64 P, [%1], 0;\n\t"
        "selp.b32 %0, 1, 0, P;\n\t}"
        : "=r"(done) : "r"(mbar_a) : "memory");
    if (!done) {
        asm volatile(
            "{\n\t.reg .pred P;\n\t"
            "WL_%=:\n\t"
            "mbarrier.try_wait.parity.acquire.cta.shared::cta.b64 P, [%0], 0, 0x989680;\n\t"
            "@P bra.uni WD_%=;\n\t"
            "bra.uni WL_%=;\n\t"
            "WD_%=:\n\t}"
            :: "r"(mbar_a) : "memory");
    }
}

__global__ __launch_bounds__(NTHR, 1) void MNB_455266533601_kernel(
    const void* __restrict__ text_raw,
    const float* __restrict__ w_weight,
    const float* __restrict__ w_bias,
    float* __restrict__ out)
{
    extern __shared__ float smem[];
    float* sw  = smem;                     // [V_SZ] staged table
    float* red = smem + V_SZ;              // [NGRP][PHR_PER_BLK]
    unsigned long long* mbar =
        (unsigned long long*)(smem + V_SZ + RED_FLOATS);   // [2]

    const int tid = threadIdx.x;
    const int p   = tid & (PHR_PER_BLK - 1);   // phrase within block
    const int g   = tid >> 5;                  // s-group
    const int b   = blockIdx.x * PHR_PER_BLK + p;
    const uint32_t mbar0_a = smem_u32(mbar);

    // ---- tid0: init mbarriers AND issue both TMA chunks immediately
    // (program order on tid0 suffices for init->TMA; the __syncthreads below
    //  orders init before every other thread's try_wait). TMA starts without
    //  waiting for the 32-warp barrier arrival spread.
    if (tid == 0) {
        asm volatile("mbarrier.init.shared.b64 [%0], 1;" :: "r"(mbar0_a) : "memory");
        asm volatile("mbarrier.init.shared.b64 [%0], 1;" :: "r"(mbar0_a + 8) : "memory");

        uint32_t dst = smem_u32(sw);
        const char* src = (const char*)w_weight;

        asm volatile("mbarrier.arrive.expect_tx.shared.b64 _, [%0], %1;"
                     :: "r"(mbar0_a), "r"((uint32_t)CH0_BYTES) : "memory");
        asm volatile(
            "cp.async.bulk.shared::cta.global.mbarrier::complete_tx::bytes "
            "[%0], [%1], %2, [%3];"
            :: "r"(dst), "l"(src), "r"((uint32_t)CH0_BYTES), "r"(mbar0_a)
            : "memory");

        asm volatile("mbarrier.arrive.expect_tx.shared.b64 _, [%0], %1;"
                     :: "r"(mbar0_a + 8), "r"((uint32_t)CH1_BYTES) : "memory");
        asm volatile(
            "cp.async.bulk.shared::cta.global.mbarrier::complete_tx::bytes "
            "[%0], [%1], %2, [%3];"
            :: "r"(dst + CH0_BYTES), "l"(src + CH0_BYTES),
               "r"((uint32_t)CH1_BYTES), "r"(mbar0_a + 8)
            : "memory");
    }
    __syncthreads();   // publishes mbarrier init to all waiters

    // ---- dtype detection: int64 buffers have zero odd 32-bit words ----
    const unsigned int* __restrict__ t32 = (const unsigned int*)text_raw;
    unsigned int probe = t32[2 * (tid & 31) + 1];
    const bool is64 = __all_sync(0xffffffffu, probe == 0u);

    // s-groups 0..7 take 7 tokens, 8..31 take 6  (8*7 + 24*6 = 200)
    const int cnt = (g < 8) ? 7 : 6;
    const int s0  = (g < 8) ? g * 7 : 56 + (g - 8) * 6;

    // ---- front-batched coalesced index loads (overlap the TMA stream) ----
    int idx[7];
    if (is64) {
        const long long* __restrict__ t = (const long long*)text_raw;
#pragma unroll
        for (int i = 0; i < 7; i++)
            if (i < cnt) idx[i] = (int)t[(size_t)(s0 + i) * B_PHR + b];
    } else {
        const int* __restrict__ t = (const int*)text_raw;
#pragma unroll
        for (int i = 0; i < 7; i++)
            if (i < cnt) idx[i] = t[(s0 + i) * B_PHR + b];
    }

    const float bias = __ldg(w_bias);

    // ---- pass A: 75% of vocab, hidden under chunk1's remaining stream ----
    float acc = 0.0f;
    mbar_wait0(mbar0_a);
#pragma unroll
    for (int i = 0; i < 7; i++)
        if (i < cnt && idx[i] < CH0_FLOATS) acc += sw[idx[i]];

    // ---- pass B: remaining 25% ----
    mbar_wait0(mbar0_a + 8);
#pragma unroll
    for (int i = 0; i < 7; i++)
        if (i < cnt && idx[i] >= CH0_FLOATS) acc += sw[idx[i]];

    // ---- reduce 32 partials per phrase ----
    red[g * PHR_PER_BLK + p] = acc;
    __syncthreads();

    if (tid < PHR_PER_BLK) {
        float sum = 0.0f;
#pragma unroll
        for (int j = 0; j < NGRP; j++) sum += red[j * PHR_PER_BLK + tid];
        out[blockIdx.x * PHR_PER_BLK + tid] = sum + bias;
    }
}

extern "C" void kernel_launch(void* const* d_in, const int* in_sizes, int n_in,
                              void* d_out, int out_size) {
    const void*  text   = d_in[0];                 // (200, 2048) int32 or int64
    const float* weight = (const float*)d_in[1];   // (1, 50000) float32
    const float* bias   = (const float*)d_in[2];   // (1,) float32
    float*       out    = (float*)d_out;           // (2048, 1) float32

    cudaFuncSetAttribute(MNB_455266533601_kernel,
                         cudaFuncAttributeMaxDynamicSharedMemorySize, SMEM_BYTES);

    MNB_455266533601_kernel<<<NBLK, NTHR, SMEM_BYTES>>>(text, weight, bias, out);
}

// round 11
// speedup vs baseline: 1.1635x; 1.1635x over previous
#include <cuda_runtime.h>
#include <stdint.h>

// out[b] = sum_{s=0}^{199} w_weight[text[s,b]] + bias
// text (200, 2048) row-major, tokens in [0, 50000)
#define S_TOK 200
#define B_PHR 2048
#define V_SZ  50000
#define STAGE_FLOATS 37500              // staged region: 150000 B (16B multiple)
#define STAGE_BYTES  (STAGE_FLOATS * 4)
#define PHR_PER_BLK 32
#define NBLK (B_PHR / PHR_PER_BLK)      // 64 blocks, single wave
#define NTHR 1024
#define NGRP 32
#define RED_FLOATS (NGRP * PHR_PER_BLK) // 1024
#define SMEM_BYTES (STAGE_BYTES + RED_FLOATS * 4 + 16)

__device__ __forceinline__ uint32_t smem_u32(const void* p) {
    uint32_t a;
    asm("{ .reg .u64 t; cvta.to.shared.u64 t, %1; cvt.u32.u64 %0, t; }"
        : "=r"(a) : "l"(p));
    return a;
}

__device__ __forceinline__ void mbar_wait0(uint32_t mbar_a) {
    uint32_t done;
    asm volatile(
        "{\n\t.reg .pred P;\n\t"
        "mbarrier.try_wait.parity.acquire.cta.shared::cta.b64 P, [%1], 0;\n\t"
        "selp.b32 %0, 1, 0, P;\n\t}"
        : "=r"(done) : "r"(mbar_a) : "memory");
    if (!done) {
        asm volatile(
            "{\n\t.reg .pred P;\n\t"
            "WL_%=:\n\t"
            "mbarrier.try_wait.parity.acquire.cta.shared::cta.b64 P, [%0], 0, 0x989680;\n\t"
            "@P bra.uni WD_%=;\n\t"
            "bra.uni WL_%=;\n\t"
            "WD_%=:\n\t}"
            :: "r"(mbar_a) : "memory");
    }
}

__global__ __launch_bounds__(NTHR, 1) void MNB_455266533601_kernel(
    const void* __restrict__ text_raw,
    const float* __restrict__ w_weight,
    const float* __restrict__ w_bias,
    float* __restrict__ out)
{
    extern __shared__ float smem[];
    float* sw  = smem;                         // [STAGE_FLOATS] staged low vocab
    float* red = smem + STAGE_FLOATS;          // [NGRP][PHR_PER_BLK]
    unsigned long long* mbar =
        (unsigned long long*)(smem + STAGE_FLOATS + RED_FLOATS);

    const int tid = threadIdx.x;
    const int p   = tid & (PHR_PER_BLK - 1);   // phrase within block
    const int g   = tid >> 5;                  // s-group
    const int b   = blockIdx.x * PHR_PER_BLK + p;
    const uint32_t mbar_a = smem_u32(mbar);

    // ---- tid0: init mbarrier and immediately issue the single TMA chunk
    // (program order suffices on tid0; __syncthreads publishes init to waiters)
    if (tid == 0) {
        asm volatile("mbarrier.init.shared.b64 [%0], 1;" :: "r"(mbar_a) : "memory");
        asm volatile("mbarrier.arrive.expect_tx.shared.b64 _, [%0], %1;"
                     :: "r"(mbar_a), "r"((uint32_t)STAGE_BYTES) : "memory");
        asm volatile(
            "cp.async.bulk.shared::cta.global.mbarrier::complete_tx::bytes "
            "[%0], [%1], %2, [%3];"
            :: "r"(smem_u32(sw)), "l"((const char*)w_weight),
               "r"((uint32_t)STAGE_BYTES), "r"(mbar_a)
            : "memory");
    }
    __syncthreads();

    // ---- dtype detection: int64 buffers have zero odd 32-bit words ----
    const unsigned int* __restrict__ t32 = (const unsigned int*)text_raw;
    unsigned int probe = t32[2 * (tid & 31) + 1];
    const bool is64 = __all_sync(0xffffffffu, probe == 0u);

    // s-groups 0..7 take 7 tokens, 8..31 take 6  (8*7 + 24*6 = 200)
    const int cnt = (g < 8) ? 7 : 6;
    const int s0  = (g < 8) ? g * 7 : 56 + (g - 8) * 6;

    // ---- front-batched coalesced index loads (overlap the TMA stream) ----
    int idx[7];
    if (is64) {
        const long long* __restrict__ t = (const long long*)text_raw;
#pragma unroll
        for (int i = 0; i < 7; i++)
            if (i < cnt) idx[i] = (int)t[(size_t)(s0 + i) * B_PHR + b];
    } else {
        const int* __restrict__ t = (const int*)text_raw;
#pragma unroll
        for (int i = 0; i < 7; i++)
            if (i < cnt) idx[i] = t[(s0 + i) * B_PHR + b];
    }

    const float bias = __ldg(w_bias);

    // ---- direct L2 gathers for the UNSTAGED upper vocab (~25% of tokens),
    //      issued while the TMA stream is still in flight (LSU pipe is idle) ----
    float acc = 0.0f;
#pragma unroll
    for (int i = 0; i < 7; i++)
        if (i < cnt && idx[i] >= STAGE_FLOATS) acc += __ldg(&w_weight[idx[i]]);

    // ---- wait for the staged region, then gather the low 75% from smem ----
    mbar_wait0(mbar_a);
#pragma unroll
    for (int i = 0; i < 7; i++)
        if (i < cnt && idx[i] < STAGE_FLOATS) acc += sw[idx[i]];

    // ---- reduce 32 partials per phrase ----
    red[g * PHR_PER_BLK + p] = acc;
    __syncthreads();

    if (tid < PHR_PER_BLK) {
        float sum = 0.0f;
#pragma unroll
        for (int j = 0; j < NGRP; j++) sum += red[j * PHR_PER_BLK + tid];
        out[blockIdx.x * PHR_PER_BLK + tid] = sum + bias;
    }
}

extern "C" void kernel_launch(void* const* d_in, const int* in_sizes, int n_in,
                              void* d_out, int out_size) {
    const void*  text   = d_in[0];                 // (200, 2048) int32 or int64
    const float* weight = (const float*)d_in[1];   // (1, 50000) float32
    const float* bias   = (const float*)d_in[2];   // (1,) float32
    float*       out    = (float*)d_out;           // (2048, 1) float32

    cudaFuncSetAttribute(MNB_455266533601_kernel,
                         cudaFuncAttributeMaxDynamicSharedMemorySize, SMEM_BYTES);

    MNB_455266533601_kernel<<<NBLK, NTHR, SMEM_BYTES>>>(text, weight, bias, out);
}

// round 12
// speedup vs baseline: 1.1691x; 1.0048x over previous
#include <cuda_runtime.h>
#include <stdint.h>

// out[b] = sum_{s=0}^{199} w_weight[text[s,b]] + bias
// text (200, 2048) row-major, tokens in [0, 50000)
//
// Converged design (R9): 64 CTAs x 1024 thr, full 200KB fp32 table staged in
// smem via two 100KB TMA bulk chunks with per-chunk mbarriers; coalesced index
// loads front-batched under the TMA stream; gather pass A (low vocab half)
// overlaps chunk 1's stream; pass B after chunk 1 lands; smem tree reduce.
#define S_TOK 200
#define B_PHR 2048
#define V_SZ  50000
#define V_HALF 25000                    // two TMA chunks of 100KB
#define HALF_BYTES (V_HALF * 4)         // 100000 B (16B multiple)
#define PHR_PER_BLK 32
#define NBLK (B_PHR / PHR_PER_BLK)      // 64 blocks, single wave
#define NTHR 1024
#define NGRP 32
#define RED_FLOATS (NGRP * PHR_PER_BLK) // 1024
#define SMEM_BYTES (V_SZ * 4 + RED_FLOATS * 4 + 2 * 8 + 8)

__device__ __forceinline__ uint32_t smem_u32(const void* p) {
    uint32_t a;
    asm("{ .reg .u64 t; cvta.to.shared.u64 t, %1; cvt.u32.u64 %0, t; }"
        : "=r"(a) : "l"(p));
    return a;
}

__device__ __forceinline__ void mbar_wait0(uint32_t mbar_a) {
    uint32_t done;
    asm volatile(
        "{\n\t.reg .pred P;\n\t"
        "mbarrier.try_wait.parity.acquire.cta.shared::cta.b64 P, [%1], 0;\n\t"
        "selp.b32 %0, 1, 0, P;\n\t}"
        : "=r"(done) : "r"(mbar_a) : "memory");
    if (!done) {
        asm volatile(
            "{\n\t.reg .pred P;\n\t"
            "WL_%=:\n\t"
            "mbarrier.try_wait.parity.acquire.cta.shared::cta.b64 P, [%0], 0, 0x989680;\n\t"
            "@P bra.uni WD_%=;\n\t"
            "bra.uni WL_%=;\n\t"
            "WD_%=:\n\t}"
            :: "r"(mbar_a) : "memory");
    }
}

__global__ __launch_bounds__(NTHR, 1) void MNB_455266533601_kernel(
    const void* __restrict__ text_raw,
    const float* __restrict__ w_weight,
    const float* __restrict__ w_bias,
    float* __restrict__ out)
{
    extern __shared__ float smem[];
    float* sw  = smem;                     // [V_SZ] staged table
    float* red = smem + V_SZ;              // [NGRP][PHR_PER_BLK]
    unsigned long long* mbar =
        (unsigned long long*)(smem + V_SZ + RED_FLOATS);   // [2]

    const int tid = threadIdx.x;
    const int p   = tid & (PHR_PER_BLK - 1);   // phrase within block
    const int g   = tid >> 5;                  // s-group
    const int b   = blockIdx.x * PHR_PER_BLK + p;
    const uint32_t mbar0_a = smem_u32(mbar);

    // ---- init both mbarriers, one sync, then issue both TMA chunks ----
    if (tid == 0) {
        asm volatile("mbarrier.init.shared.b64 [%0], 1;" :: "r"(mbar0_a) : "memory");
        asm volatile("mbarrier.init.shared.b64 [%0], 1;" :: "r"(mbar0_a + 8) : "memory");
    }
    __syncthreads();   // init visible to all waiters (and to the TMA completes)

    if (tid == 0) {
        uint32_t dst = smem_u32(sw);
        const char* src = (const char*)w_weight;
#pragma unroll
        for (int c = 0; c < 2; c++) {
            asm volatile("mbarrier.arrive.expect_tx.shared.b64 _, [%0], %1;"
                         :: "r"(mbar0_a + 8 * c), "r"((uint32_t)HALF_BYTES) : "memory");
            asm volatile(
                "cp.async.bulk.shared::cta.global.mbarrier::complete_tx::bytes "
                "[%0], [%1], %2, [%3];"
                :: "r"(dst + c * HALF_BYTES), "l"(src + (size_t)c * HALF_BYTES),
                   "r"((uint32_t)HALF_BYTES), "r"(mbar0_a + 8 * c)
                : "memory");
        }
    }

    // ---- dtype detection: int64 buffers have zero odd 32-bit words ----
    const unsigned int* __restrict__ t32 = (const unsigned int*)text_raw;
    unsigned int probe = t32[2 * (tid & 31) + 1];
    const bool is64 = __all_sync(0xffffffffu, probe == 0u);

    // s-groups 0..7 take 7 tokens, 8..31 take 6  (8*7 + 24*6 = 200)
    const int cnt = (g < 8) ? 7 : 6;
    const int s0  = (g < 8) ? g * 7 : 56 + (g - 8) * 6;

    // ---- front-batched coalesced index loads (overlap the TMA stream) ----
    int idx[7];
    if (is64) {
        const long long* __restrict__ t = (const long long*)text_raw;
#pragma unroll
        for (int i = 0; i < 7; i++)
            if (i < cnt) idx[i] = (int)t[(size_t)(s0 + i) * B_PHR + b];
    } else {
        const int* __restrict__ t = (const int*)text_raw;
#pragma unroll
        for (int i = 0; i < 7; i++)
            if (i < cnt) idx[i] = t[(s0 + i) * B_PHR + b];
    }

    const float bias = __ldg(w_bias);

    // ---- pass A: lower half, while the upper half is still streaming ----
    float acc = 0.0f;
    mbar_wait0(mbar0_a);
#pragma unroll
    for (int i = 0; i < 7; i++)
        if (i < cnt && idx[i] < V_HALF) acc += sw[idx[i]];

    // ---- pass B: upper half ----
    mbar_wait0(mbar0_a + 8);
#pragma unroll
    for (int i = 0; i < 7; i++)
        if (i < cnt && idx[i] >= V_HALF) acc += sw[idx[i]];

    // ---- reduce 32 partials per phrase ----
    red[g * PHR_PER_BLK + p] = acc;
    __syncthreads();

    if (tid < PHR_PER_BLK) {
        float sum = 0.0f;
#pragma unroll
        for (int j = 0; j < NGRP; j++) sum += red[j * PHR_PER_BLK + tid];
        out[blockIdx.x * PHR_PER_BLK + tid] = sum + bias;
    }
}

extern "C" void kernel_launch(void* const* d_in, const int* in_sizes, int n_in,
                              void* d_out, int out_size) {
    const void*  text   = d_in[0];                 // (200, 2048) int32 or int64
    const float* weight = (const float*)d_in[1];   // (1, 50000) float32
    const float* bias   = (const float*)d_in[2];   // (1,) float32
    float*       out    = (float*)d_out;           // (2048, 1) float32

    cudaFuncSetAttribute(MNB_455266533601_kernel,
                         cudaFuncAttributeMaxDynamicSharedMemorySize, SMEM_BYTES);
    // Hint: keep the full carveout as shared memory so the launch never
    // reconfigures the L1/smem split (capture-time call; no-op on replay).
    cudaFuncSetAttribute(MNB_455266533601_kernel,
                         cudaFuncAttributePreferredSharedMemoryCarveout,
                         cudaSharedmemCarveoutMaxShared);

    MNB_455266533601_kernel<<<NBLK, NTHR, SMEM_BYTES>>>(text, weight, bias, out);
}